// round 16
// baseline (speedup 1.0000x reference)
#include <cuda_runtime.h>
#include <cuda_bf16.h>
#include <cstdint>

// DenseGridNet via warp-level mma.sync bf16 (m16n8k16), split-bf16 x3.
// R16: M=32 per warp — two m16 halves share every B-fragment LDS (halves the
// dominant L1 traffic). THREADS=128, 3 CTAs/SM. a2-lo frags round-trip via
// warp-private smem to bound registers. Lane-coop cp.async gather (R15).

#define THREADS 128
#define NCTA 444
#define AS2 40    // A0 row stride (words): conflict-free frag ld/st
#define GQ 13     // staged quads per point

struct __align__(16) Smem {
    uint4 B1[8 * 32];
    uint4 B2[32 * 32];
    uint4 B3[4 * 32];
    float b2s[64], b3s[8];
    uint32_t A0h[4][8 * AS2];
    uint32_t A0l[4][8 * AS2];
    uint32_t A2l[4][2][4][4][32];   // [warp][m][kk][word][lane]
    float4 G[4][32 * GQ];           // per-warp staged texels
};
#define SMEM_BYTES ((int)sizeof(Smem))

__device__ __forceinline__ uint32_t smaddr(const void* p) {
    uint32_t a;
    asm("{ .reg .u64 t; cvta.to.shared.u64 t, %1; cvt.u32.u64 %0, t; }"
        : "=r"(a) : "l"(p));
    return a;
}
#define CPA16(sm, gm) \
    asm volatile("cp.async.ca.shared.global [%0], [%1], 16;" \
                 :: "r"(sm), "l"(gm) : "memory")
#define CPA_COMMIT()   asm volatile("cp.async.commit_group;" ::: "memory")
#define CPA_WAIT_ALL() asm volatile("cp.async.wait_group 0;" ::: "memory")

__device__ __forceinline__ void splitpack(float v0, float v1,
                                          uint32_t& hi, uint32_t& lo) {
    asm("cvt.rn.bf16x2.f32 %0, %1, %2;" : "=r"(hi) : "f"(v1), "f"(v0));
    float r0 = __uint_as_float(hi << 16);
    float r1 = __uint_as_float(hi & 0xFFFF0000u);
    asm("cvt.rn.bf16x2.f32 %0, %1, %2;" : "=r"(lo) : "f"(v1 - r1), "f"(v0 - r0));
}
__device__ __forceinline__ void splitval(float v, uint32_t pos16,
                                         uint32_t& hi, uint32_t& lo) {
    __nv_bfloat16 h = __float2bfloat16(v);
    float r = v - __bfloat162float(h);
    __nv_bfloat16 l = __float2bfloat16(r);
    uint16_t hb, lb;
    __builtin_memcpy(&hb, &h, 2);
    __builtin_memcpy(&lb, &l, 2);
    hi |= (uint32_t)hb << pos16;
    lo |= (uint32_t)lb << pos16;
}

__device__ __forceinline__ void mma16816(float c[4], const uint32_t a[4],
                                         uint32_t b0, uint32_t b1) {
    asm volatile(
        "mma.sync.aligned.m16n8k16.row.col.f32.bf16.bf16.f32 "
        "{%0,%1,%2,%3}, {%4,%5,%6,%7}, {%8,%9}, {%0,%1,%2,%3};"
        : "+f"(c[0]), "+f"(c[1]), "+f"(c[2]), "+f"(c[3])
        : "r"(a[0]), "r"(a[1]), "r"(a[2]), "r"(a[3]), "r"(b0), "r"(b1));
}

__device__ __forceinline__ const float4* tex_addr(const float4* __restrict__ tab,
                                                  int res, float u, float v,
                                                  int t4) {
    float sx = u * (float)res, sy = v * (float)res;
    int x0 = (int)sx, y0 = (int)sy;            // truncation == astype(int32)
    int xi = (t4 & 1) ? min(x0 + 1, res) : min(x0, res);
    int yi = (t4 & 2) ? min(y0 + 1, res) : min(y0, res);
    return tab + yi * res + xi;                // reference row stride == res
}

__device__ __forceinline__ float4 blend(float4 v00, float4 v10, float4 v01,
                                        float4 v11, int res, float u, float v) {
    float sx = u * (float)res, sy = v * (float)res;
    int x0 = (int)sx, y0 = (int)sy;
    float wx = sx - (float)x0, wy = sy - (float)y0;
    float omwx = 1.0f - wx, omwy = 1.0f - wy;
    float4 o; float t, c;
    t = v00.x*omwx + v10.x*wx; c = v01.x*omwx + v11.x*wx; o.x = t*omwy + c*wy;
    t = v00.y*omwx + v10.y*wx; c = v01.y*omwx + v11.y*wx; o.y = t*omwy + c*wy;
    t = v00.z*omwx + v10.z*wx; c = v01.z*omwx + v11.z*wx; o.z = t*omwy + c*wy;
    t = v00.w*omwx + v10.w*wx; c = v01.w*omwx + v11.w*wx; o.w = t*omwy + c*wy;
    return o;
}

// layer-1 weight, permuted K (matches A0 kpair layout); k==14 -> bias row.
__device__ __forceinline__ float w1val(const float* w1, const float* b1,
                                       int k, int nn) {
    if (k < 5)  return w1[k * 64 + nn];
    if (k == 5 || k == 15) return 0.0f;
    if (k <= 13) return w1[(k - 1) * 64 + nn];
    return b1[nn];
}

__global__ __launch_bounds__(THREADS, 3)
void densegrid_kernel(const float* __restrict__ x,
                      const float4* __restrict__ emb0,
                      const float4* __restrict__ emb1,
                      const float4* __restrict__ emb2,
                      const float* __restrict__ w1, const float* __restrict__ b1,
                      const float* __restrict__ w2, const float* __restrict__ b2,
                      const float* __restrict__ w3, const float* __restrict__ b3,
                      float* __restrict__ out, int n) {
    extern __shared__ char smraw[];
    Smem& s = *reinterpret_cast<Smem*>(smraw);

    const int tid  = threadIdx.x;
    const int wid  = tid >> 5;
    const int lane = tid & 31;
    const int grp  = lane >> 2;
    const int t4   = lane & 3;
    const int pb   = lane >> 1;    // blend point within 16-pt round
    const int hbr  = lane & 1;     // blend half-role
    const int pg   = lane >> 2;    // gather point within 8-pt round

    // ---- one-time weight fragment staging ----
    for (int i = tid; i < 32 * 32; i += THREADS) {
        int ln = i & 31, gkk = i >> 5;
        int kk = gkk & 3, g = gkk >> 2;
        int tt = ln & 3, gp = ln >> 2;
        int nn = 8 * g + gp, k0 = 16 * kk + 2 * tt;
        uint32_t h0 = 0, l0 = 0, h1 = 0, l1 = 0;
        splitval(w2[(k0 + 0) * 64 + nn], 0,  h0, l0);
        splitval(w2[(k0 + 1) * 64 + nn], 16, h0, l0);
        splitval(w2[(k0 + 8) * 64 + nn], 0,  h1, l1);
        splitval(w2[(k0 + 9) * 64 + nn], 16, h1, l1);
        s.B2[i] = make_uint4(h0, h1, l0, l1);
    }
    for (int i = tid; i < 8 * 32; i += THREADS) {
        int ln = i & 31, g = i >> 5;
        int tt = ln & 3, gp = ln >> 2;
        int nn = 8 * g + gp, k0 = 2 * tt;
        uint32_t h0 = 0, l0 = 0, h1 = 0, l1 = 0;
        splitval(w1val(w1, b1, k0 + 0, nn), 0,  h0, l0);
        splitval(w1val(w1, b1, k0 + 1, nn), 16, h0, l0);
        splitval(w1val(w1, b1, k0 + 8, nn), 0,  h1, l1);
        splitval(w1val(w1, b1, k0 + 9, nn), 16, h1, l1);
        s.B1[i] = make_uint4(h0, h1, l0, l1);
    }
    for (int i = tid; i < 4 * 32; i += THREADS) {
        int ln = i & 31, kk = i >> 5;
        int tt = ln & 3, gp = ln >> 2;
        int k0 = 16 * kk + 2 * tt;
        uint32_t h0 = 0, l0 = 0, h1 = 0, l1 = 0;
        if (gp < 3) {
            splitval(w3[(k0 + 0) * 3 + gp], 0,  h0, l0);
            splitval(w3[(k0 + 1) * 3 + gp], 16, h0, l0);
            splitval(w3[(k0 + 8) * 3 + gp], 0,  h1, l1);
            splitval(w3[(k0 + 9) * 3 + gp], 16, h1, l1);
        }
        s.B3[i] = make_uint4(h0, h1, l0, l1);
    }
    for (int i = tid; i < 64; i += THREADS) s.b2s[i] = b2[i];
    if (tid < 8) s.b3s[tid] = (tid < 3) ? b3[tid] : 0.0f;
    __syncthreads();

    // bias row (kpair 7) for 32 points
    s.A0h[wid][7 * AS2 + lane] = 0x00003F80u;
    s.A0l[wid][7 * AS2 + lane] = 0u;
    __syncwarp();

    const int ntw = (n + 31) >> 5;
    const int wstride = gridDim.x * 4;
    int t = blockIdx.x * 4 + wid;

    const uint32_t gbase = smaddr(&s.G[wid][0]);

    float ug[4], vg[4], ub[2], vb[2], idb[2];
    #pragma unroll
    for (int r = 0; r < 4; r++) { ug[r] = 0.f; vg[r] = 0.f; }
    #pragma unroll
    for (int r = 0; r < 2; r++) { ub[r] = 0.f; vb[r] = 0.f; idb[r] = 0.f; }

    if (t < ntw) {
        #pragma unroll
        for (int r = 0; r < 4; r++) {
            int idx = min(t * 32 + r * 8 + pg, n - 1);
            ug[r] = x[idx * 3 + 1]; vg[r] = x[idx * 3 + 2];
        }
        #pragma unroll
        for (int r = 0; r < 2; r++) {
            int idx = min(t * 32 + r * 16 + pb, n - 1);
            idb[r] = x[idx * 3 + 0]; ub[r] = x[idx * 3 + 1]; vb[r] = x[idx * 3 + 2];
        }
        #pragma unroll
        for (int r = 0; r < 4; r++) {
            int pt = r * 8 + pg;
            CPA16(gbase + (pt * GQ + 0 + t4) * 16, tex_addr(emb0, 512, ug[r], vg[r], t4));
            CPA16(gbase + (pt * GQ + 4 + t4) * 16, tex_addr(emb1, 264, ug[r], vg[r], t4));
            CPA16(gbase + (pt * GQ + 8 + t4) * 16, tex_addr(emb2, 16,  ug[r], vg[r], t4));
        }
    }
    CPA_COMMIT();

    for (; t < ntw; t += wstride) {
        const int tn = t + wstride;

        // prefetch next-tile coords (latency rides under blend/layer1)
        float ugn[4], vgn[4], ubn[2], vbn[2], idbn[2];
        #pragma unroll
        for (int r = 0; r < 4; r++) { ugn[r] = 0.f; vgn[r] = 0.f; }
        #pragma unroll
        for (int r = 0; r < 2; r++) { ubn[r] = 0.f; vbn[r] = 0.f; idbn[r] = 0.f; }
        if (tn < ntw) {
            #pragma unroll
            for (int r = 0; r < 4; r++) {
                int idx = min(tn * 32 + r * 8 + pg, n - 1);
                ugn[r] = x[idx * 3 + 1]; vgn[r] = x[idx * 3 + 2];
            }
            #pragma unroll
            for (int r = 0; r < 2; r++) {
                int idx = min(tn * 32 + r * 16 + pb, n - 1);
                idbn[r] = x[idx * 3 + 0]; ubn[r] = x[idx * 3 + 1]; vbn[r] = x[idx * 3 + 2];
            }
        }

        CPA_WAIT_ALL();
        __syncwarp();

        // ---- blend -> pre-split A0, two 16-pt rounds ----
        uint32_t* Ah = s.A0h[wid];
        uint32_t* Al = s.A0l[wid];
        #pragma unroll
        for (int r = 0; r < 2; r++) {
            int pt = r * 16 + pb;
            const float4* g = &s.G[wid][pt * GQ];
            uint32_t hh, ll;
            if (hbr == 0) {
                float4 f0 = blend(g[0], g[1], g[2], g[3], 512, ub[r], vb[r]);
                splitpack(idb[r], f0.x, hh, ll); Ah[0 * AS2 + pt] = hh; Al[0 * AS2 + pt] = ll;
                splitpack(f0.y, f0.z, hh, ll);   Ah[1 * AS2 + pt] = hh; Al[1 * AS2 + pt] = ll;
                splitpack(f0.w, 0.0f, hh, ll);   Ah[2 * AS2 + pt] = hh; Al[2 * AS2 + pt] = ll;
            } else {
                float4 f1 = blend(g[4], g[5], g[6], g[7], 264, ub[r], vb[r]);
                float4 f2 = blend(g[8], g[9], g[10], g[11], 16, ub[r], vb[r]);
                splitpack(f1.x, f1.y, hh, ll); Ah[3 * AS2 + pt] = hh; Al[3 * AS2 + pt] = ll;
                splitpack(f1.z, f1.w, hh, ll); Ah[4 * AS2 + pt] = hh; Al[4 * AS2 + pt] = ll;
                splitpack(f2.x, f2.y, hh, ll); Ah[5 * AS2 + pt] = hh; Al[5 * AS2 + pt] = ll;
                splitpack(f2.z, f2.w, hh, ll); Ah[6 * AS2 + pt] = hh; Al[6 * AS2 + pt] = ll;
            }
        }
        __syncwarp();

        // ---- A0 fragments for both halves ----
        uint32_t a0h[2][4], a0l[2][4];
        #pragma unroll
        for (int m = 0; m < 2; m++) {
            int pl = m * 16 + grp;
            a0h[m][0] = Ah[t4 * AS2 + pl];           a0l[m][0] = Al[t4 * AS2 + pl];
            a0h[m][1] = Ah[t4 * AS2 + pl + 8];       a0l[m][1] = Al[t4 * AS2 + pl + 8];
            a0h[m][2] = Ah[(t4 + 4) * AS2 + pl];     a0l[m][2] = Al[(t4 + 4) * AS2 + pl];
            a0h[m][3] = Ah[(t4 + 4) * AS2 + pl + 8]; a0l[m][3] = Al[(t4 + 4) * AS2 + pl + 8];
        }

        // ---- issue cp.async gathers for tile tn (overlaps all 3 layers) ----
        if (tn < ntw) {
            #pragma unroll
            for (int r = 0; r < 4; r++) {
                int pt = r * 8 + pg;
                CPA16(gbase + (pt * GQ + 0 + t4) * 16, tex_addr(emb0, 512, ugn[r], vgn[r], t4));
                CPA16(gbase + (pt * GQ + 4 + t4) * 16, tex_addr(emb1, 264, ugn[r], vgn[r], t4));
                CPA16(gbase + (pt * GQ + 8 + t4) * 16, tex_addr(emb2, 16,  ugn[r], vgn[r], t4));
            }
        }
        CPA_COMMIT();

        // ---- layer 1: 16 -> 64 (bias row folded), relu -> A1 frags ----
        uint32_t a1h[2][4][4], a1l[2][4][4];
        #pragma unroll
        for (int g = 0; g < 8; g++) {
            uint4 b = s.B1[g * 32 + lane];
            int kk = g >> 1, hf = g & 1;
            #pragma unroll
            for (int m = 0; m < 2; m++) {
                float c[4] = {0.0f, 0.0f, 0.0f, 0.0f};
                mma16816(c, a0h[m], b.x, b.y);
                mma16816(c, a0h[m], b.z, b.w);
                mma16816(c, a0l[m], b.x, b.y);
                splitpack(fmaxf(c[0], 0.0f), fmaxf(c[1], 0.0f),
                          a1h[m][kk][2 * hf + 0], a1l[m][kk][2 * hf + 0]);
                splitpack(fmaxf(c[2], 0.0f), fmaxf(c[3], 0.0f),
                          a1h[m][kk][2 * hf + 1], a1l[m][kk][2 * hf + 1]);
            }
        }

        // ---- layer 2: 64 -> 64, bias+relu; a2 hi in regs, lo to smem ----
        uint32_t a2h[2][4][4];
        #pragma unroll
        for (int g = 0; g < 8; g++) {
            uint4 bq0 = s.B2[(g * 4 + 0) * 32 + lane];
            uint4 bq1 = s.B2[(g * 4 + 1) * 32 + lane];
            uint4 bq2 = s.B2[(g * 4 + 2) * 32 + lane];
            uint4 bq3 = s.B2[(g * 4 + 3) * 32 + lane];
            float2 bb = *(const float2*)&s.b2s[8 * g + 2 * t4];
            int kk2 = g >> 1, hf = g & 1;
            #pragma unroll
            for (int m = 0; m < 2; m++) {
                float c[4];
                c[0] = bb.x; c[1] = bb.y; c[2] = bb.x; c[3] = bb.y;
                mma16816(c, a1h[m][0], bq0.x, bq0.y);
                mma16816(c, a1h[m][0], bq0.z, bq0.w);
                mma16816(c, a1l[m][0], bq0.x, bq0.y);
                mma16816(c, a1h[m][1], bq1.x, bq1.y);
                mma16816(c, a1h[m][1], bq1.z, bq1.w);
                mma16816(c, a1l[m][1], bq1.x, bq1.y);
                mma16816(c, a1h[m][2], bq2.x, bq2.y);
                mma16816(c, a1h[m][2], bq2.z, bq2.w);
                mma16816(c, a1l[m][2], bq2.x, bq2.y);
                mma16816(c, a1h[m][3], bq3.x, bq3.y);
                mma16816(c, a1h[m][3], bq3.z, bq3.w);
                mma16816(c, a1l[m][3], bq3.x, bq3.y);
                uint32_t h01, l01, h23, l23;
                splitpack(fmaxf(c[0], 0.0f), fmaxf(c[1], 0.0f), h01, l01);
                splitpack(fmaxf(c[2], 0.0f), fmaxf(c[3], 0.0f), h23, l23);
                a2h[m][kk2][2 * hf + 0] = h01;
                a2h[m][kk2][2 * hf + 1] = h23;
                s.A2l[wid][m][kk2][2 * hf + 0][lane] = l01;
                s.A2l[wid][m][kk2][2 * hf + 1][lane] = l23;
            }
        }

        // ---- layer 3: 64 -> 8 (3 used), write output ----
        #pragma unroll
        for (int m = 0; m < 2; m++) {
            float c[4];
            float2 bb = *(const float2*)&s.b3s[2 * t4];
            c[0] = bb.x; c[1] = bb.y; c[2] = bb.x; c[3] = bb.y;
            #pragma unroll
            for (int kk = 0; kk < 4; kk++) {
                uint4 b = s.B3[kk * 32 + lane];
                uint32_t al[4];
                al[0] = s.A2l[wid][m][kk][0][lane];
                al[1] = s.A2l[wid][m][kk][1][lane];
                al[2] = s.A2l[wid][m][kk][2][lane];
                al[3] = s.A2l[wid][m][kk][3][lane];
                mma16816(c, a2h[m][kk], b.x, b.y);
                mma16816(c, a2h[m][kk], b.z, b.w);
                mma16816(c, al, b.x, b.y);
            }
            int p0 = t * 32 + m * 16 + grp;
            int col = 2 * t4;
            if (col < 3) {
                if (p0 < n)     out[p0 * 3 + col]       = c[0];
                if (p0 + 8 < n) out[(p0 + 8) * 3 + col] = c[2];
            }
            if (col + 1 < 3) {
                if (p0 < n)     out[p0 * 3 + col + 1]       = c[1];
                if (p0 + 8 < n) out[(p0 + 8) * 3 + col + 1] = c[3];
            }
        }

        #pragma unroll
        for (int r = 0; r < 4; r++) { ug[r] = ugn[r]; vg[r] = vgn[r]; }
        #pragma unroll
        for (int r = 0; r < 2; r++) { ub[r] = ubn[r]; vb[r] = vbn[r]; idb[r] = idbn[r]; }
    }
}

extern "C" void kernel_launch(void* const* d_in, const int* in_sizes, int n_in,
                              void* d_out, int out_size) {
    const float* x    = (const float*)d_in[0];
    const float4* e0  = (const float4*)d_in[1];
    const float4* e1  = (const float4*)d_in[2];
    const float4* e2  = (const float4*)d_in[3];
    const float* w1   = (const float*)d_in[4];
    const float* b1   = (const float*)d_in[5];
    const float* w2   = (const float*)d_in[6];
    const float* b2   = (const float*)d_in[7];
    const float* w3   = (const float*)d_in[8];
    const float* b3   = (const float*)d_in[9];
    float* out        = (float*)d_out;
    int n = in_sizes[0] / 3;
    (void)n_in; (void)out_size;
    cudaFuncSetAttribute(densegrid_kernel,
                         cudaFuncAttributeMaxDynamicSharedMemorySize, SMEM_BYTES);
    densegrid_kernel<<<NCTA, THREADS, SMEM_BYTES>>>(
        x, e0, e1, e2, w1, b1, w2, b2, w3, b3, out, n);
}

// round 17
// speedup vs baseline: 1.1162x; 1.1162x over previous
#include <cuda_runtime.h>
#include <cuda_bf16.h>
#include <cstdint>

// DenseGridNet via warp-level mma.sync bf16 (m16n8k16), split-bf16 x3.
// R17: M=32 per warp (B fragments shared across two m16 halves) at 256
// threads / 2 CTAs (16 warps/SM). Layer 3 fused into the layer-2 g-loop:
// each completed a2 k-fragment feeds its 3 layer-3 MMAs immediately and is
// discarded (no a2 registers, no A2l smem). Lane-coop cp.async gather.

#define THREADS 256
#define NCTA 444
#define AS2 40    // A0 row stride (words): conflict-free frag ld/st
#define GQ 13     // staged quads per point

struct __align__(16) Smem {
    uint4 B1[8 * 32];
    uint4 B2[32 * 32];
    uint4 B3[4 * 32];
    float b2s[64], b3s[8];
    uint32_t A0h[8][8 * AS2];
    uint32_t A0l[8][8 * AS2];
    float4 G[8][32 * GQ];           // per-warp staged texels
};
#define SMEM_BYTES ((int)sizeof(Smem))

__device__ __forceinline__ uint32_t smaddr(const void* p) {
    uint32_t a;
    asm("{ .reg .u64 t; cvta.to.shared.u64 t, %1; cvt.u32.u64 %0, t; }"
        : "=r"(a) : "l"(p));
    return a;
}
#define CPA16(sm, gm) \
    asm volatile("cp.async.ca.shared.global [%0], [%1], 16;" \
                 :: "r"(sm), "l"(gm) : "memory")
#define CPA_COMMIT()   asm volatile("cp.async.commit_group;" ::: "memory")
#define CPA_WAIT_ALL() asm volatile("cp.async.wait_group 0;" ::: "memory")

__device__ __forceinline__ void splitpack(float v0, float v1,
                                          uint32_t& hi, uint32_t& lo) {
    asm("cvt.rn.bf16x2.f32 %0, %1, %2;" : "=r"(hi) : "f"(v1), "f"(v0));
    float r0 = __uint_as_float(hi << 16);
    float r1 = __uint_as_float(hi & 0xFFFF0000u);
    asm("cvt.rn.bf16x2.f32 %0, %1, %2;" : "=r"(lo) : "f"(v1 - r1), "f"(v0 - r0));
}
__device__ __forceinline__ void splitval(float v, uint32_t pos16,
                                         uint32_t& hi, uint32_t& lo) {
    __nv_bfloat16 h = __float2bfloat16(v);
    float r = v - __bfloat162float(h);
    __nv_bfloat16 l = __float2bfloat16(r);
    uint16_t hb, lb;
    __builtin_memcpy(&hb, &h, 2);
    __builtin_memcpy(&lb, &l, 2);
    hi |= (uint32_t)hb << pos16;
    lo |= (uint32_t)lb << pos16;
}

__device__ __forceinline__ void mma16816(float c[4], const uint32_t a[4],
                                         uint32_t b0, uint32_t b1) {
    asm volatile(
        "mma.sync.aligned.m16n8k16.row.col.f32.bf16.bf16.f32 "
        "{%0,%1,%2,%3}, {%4,%5,%6,%7}, {%8,%9}, {%0,%1,%2,%3};"
        : "+f"(c[0]), "+f"(c[1]), "+f"(c[2]), "+f"(c[3])
        : "r"(a[0]), "r"(a[1]), "r"(a[2]), "r"(a[3]), "r"(b0), "r"(b1));
}

__device__ __forceinline__ const float4* tex_addr(const float4* __restrict__ tab,
                                                  int res, float u, float v,
                                                  int t4) {
    float sx = u * (float)res, sy = v * (float)res;
    int x0 = (int)sx, y0 = (int)sy;            // truncation == astype(int32)
    int xi = (t4 & 1) ? min(x0 + 1, res) : min(x0, res);
    int yi = (t4 & 2) ? min(y0 + 1, res) : min(y0, res);
    return tab + yi * res + xi;                // reference row stride == res
}

__device__ __forceinline__ float4 blend(float4 v00, float4 v10, float4 v01,
                                        float4 v11, int res, float u, float v) {
    float sx = u * (float)res, sy = v * (float)res;
    int x0 = (int)sx, y0 = (int)sy;
    float wx = sx - (float)x0, wy = sy - (float)y0;
    float omwx = 1.0f - wx, omwy = 1.0f - wy;
    float4 o; float t, c;
    t = v00.x*omwx + v10.x*wx; c = v01.x*omwx + v11.x*wx; o.x = t*omwy + c*wy;
    t = v00.y*omwx + v10.y*wx; c = v01.y*omwx + v11.y*wx; o.y = t*omwy + c*wy;
    t = v00.z*omwx + v10.z*wx; c = v01.z*omwx + v11.z*wx; o.z = t*omwy + c*wy;
    t = v00.w*omwx + v10.w*wx; c = v01.w*omwx + v11.w*wx; o.w = t*omwy + c*wy;
    return o;
}

// layer-1 weight, permuted K (matches A0 kpair layout); k==14 -> bias row.
__device__ __forceinline__ float w1val(const float* w1, const float* b1,
                                       int k, int nn) {
    if (k < 5)  return w1[k * 64 + nn];
    if (k == 5 || k == 15) return 0.0f;
    if (k <= 13) return w1[(k - 1) * 64 + nn];
    return b1[nn];
}

__global__ __launch_bounds__(THREADS, 2)
void densegrid_kernel(const float* __restrict__ x,
                      const float4* __restrict__ emb0,
                      const float4* __restrict__ emb1,
                      const float4* __restrict__ emb2,
                      const float* __restrict__ w1, const float* __restrict__ b1,
                      const float* __restrict__ w2, const float* __restrict__ b2,
                      const float* __restrict__ w3, const float* __restrict__ b3,
                      float* __restrict__ out, int n) {
    extern __shared__ char smraw[];
    Smem& s = *reinterpret_cast<Smem*>(smraw);

    const int tid  = threadIdx.x;
    const int wid  = tid >> 5;
    const int lane = tid & 31;
    const int grp  = lane >> 2;
    const int t4   = lane & 3;
    const int pb   = lane >> 1;    // blend point within 16-pt round
    const int hbr  = lane & 1;     // blend half-role
    const int pg   = lane >> 2;    // gather point within 8-pt round

    // ---- one-time weight fragment staging ----
    for (int i = tid; i < 32 * 32; i += THREADS) {
        int ln = i & 31, gkk = i >> 5;
        int kk = gkk & 3, g = gkk >> 2;
        int tt = ln & 3, gp = ln >> 2;
        int nn = 8 * g + gp, k0 = 16 * kk + 2 * tt;
        uint32_t h0 = 0, l0 = 0, h1 = 0, l1 = 0;
        splitval(w2[(k0 + 0) * 64 + nn], 0,  h0, l0);
        splitval(w2[(k0 + 1) * 64 + nn], 16, h0, l0);
        splitval(w2[(k0 + 8) * 64 + nn], 0,  h1, l1);
        splitval(w2[(k0 + 9) * 64 + nn], 16, h1, l1);
        s.B2[i] = make_uint4(h0, h1, l0, l1);
    }
    for (int i = tid; i < 8 * 32; i += THREADS) {
        int ln = i & 31, g = i >> 5;
        int tt = ln & 3, gp = ln >> 2;
        int nn = 8 * g + gp, k0 = 2 * tt;
        uint32_t h0 = 0, l0 = 0, h1 = 0, l1 = 0;
        splitval(w1val(w1, b1, k0 + 0, nn), 0,  h0, l0);
        splitval(w1val(w1, b1, k0 + 1, nn), 16, h0, l0);
        splitval(w1val(w1, b1, k0 + 8, nn), 0,  h1, l1);
        splitval(w1val(w1, b1, k0 + 9, nn), 16, h1, l1);
        s.B1[i] = make_uint4(h0, h1, l0, l1);
    }
    for (int i = tid; i < 4 * 32; i += THREADS) {
        int ln = i & 31, kk = i >> 5;
        int tt = ln & 3, gp = ln >> 2;
        int k0 = 16 * kk + 2 * tt;
        uint32_t h0 = 0, l0 = 0, h1 = 0, l1 = 0;
        if (gp < 3) {
            splitval(w3[(k0 + 0) * 3 + gp], 0,  h0, l0);
            splitval(w3[(k0 + 1) * 3 + gp], 16, h0, l0);
            splitval(w3[(k0 + 8) * 3 + gp], 0,  h1, l1);
            splitval(w3[(k0 + 9) * 3 + gp], 16, h1, l1);
        }
        s.B3[i] = make_uint4(h0, h1, l0, l1);
    }
    for (int i = tid; i < 64; i += THREADS) s.b2s[i] = b2[i];
    if (tid < 8) s.b3s[tid] = (tid < 3) ? b3[tid] : 0.0f;
    __syncthreads();

    // bias row (kpair 7) for this warp's 32 points
    s.A0h[wid][7 * AS2 + lane] = 0x00003F80u;
    s.A0l[wid][7 * AS2 + lane] = 0u;
    __syncwarp();

    const int ntw = (n + 31) >> 5;
    const int wstride = gridDim.x * 8;
    int t = blockIdx.x * 8 + wid;

    const uint32_t gbase = smaddr(&s.G[wid][0]);

    // carried blend coords for tile t
    float ub[2], vb[2], idb[2];
    #pragma unroll
    for (int r = 0; r < 2; r++) { ub[r] = 0.f; vb[r] = 0.f; idb[r] = 0.f; }

    if (t < ntw) {
        #pragma unroll
        for (int r = 0; r < 2; r++) {
            int idx = min(t * 32 + r * 16 + pb, n - 1);
            idb[r] = x[idx * 3 + 0]; ub[r] = x[idx * 3 + 1]; vb[r] = x[idx * 3 + 2];
        }
        #pragma unroll
        for (int r = 0; r < 4; r++) {
            int idx = min(t * 32 + r * 8 + pg, n - 1);
            float u = x[idx * 3 + 1], v = x[idx * 3 + 2];
            int pt = r * 8 + pg;
            CPA16(gbase + (pt * GQ + 0 + t4) * 16, tex_addr(emb0, 512, u, v, t4));
            CPA16(gbase + (pt * GQ + 4 + t4) * 16, tex_addr(emb1, 264, u, v, t4));
            CPA16(gbase + (pt * GQ + 8 + t4) * 16, tex_addr(emb2, 16,  u, v, t4));
        }
    }
    CPA_COMMIT();

    for (; t < ntw; t += wstride) {
        const int tn = t + wstride;

        CPA_WAIT_ALL();
        __syncwarp();

        // ---- blend -> pre-split A0, two 16-pt rounds ----
        uint32_t* Ah = s.A0h[wid];
        uint32_t* Al = s.A0l[wid];
        #pragma unroll
        for (int r = 0; r < 2; r++) {
            int pt = r * 16 + pb;
            const float4* g = &s.G[wid][pt * GQ];
            uint32_t hh, ll;
            if (hbr == 0) {
                float4 f0 = blend(g[0], g[1], g[2], g[3], 512, ub[r], vb[r]);
                splitpack(idb[r], f0.x, hh, ll); Ah[0 * AS2 + pt] = hh; Al[0 * AS2 + pt] = ll;
                splitpack(f0.y, f0.z, hh, ll);   Ah[1 * AS2 + pt] = hh; Al[1 * AS2 + pt] = ll;
                splitpack(f0.w, 0.0f, hh, ll);   Ah[2 * AS2 + pt] = hh; Al[2 * AS2 + pt] = ll;
            } else {
                float4 f1 = blend(g[4], g[5], g[6], g[7], 264, ub[r], vb[r]);
                float4 f2 = blend(g[8], g[9], g[10], g[11], 16, ub[r], vb[r]);
                splitpack(f1.x, f1.y, hh, ll); Ah[3 * AS2 + pt] = hh; Al[3 * AS2 + pt] = ll;
                splitpack(f1.z, f1.w, hh, ll); Ah[4 * AS2 + pt] = hh; Al[4 * AS2 + pt] = ll;
                splitpack(f2.x, f2.y, hh, ll); Ah[5 * AS2 + pt] = hh; Al[5 * AS2 + pt] = ll;
                splitpack(f2.z, f2.w, hh, ll); Ah[6 * AS2 + pt] = hh; Al[6 * AS2 + pt] = ll;
            }
        }
        __syncwarp();

        // ---- A0 fragments for both halves ----
        uint32_t a0h[2][4], a0l[2][4];
        #pragma unroll
        for (int m = 0; m < 2; m++) {
            int pl = m * 16 + grp;
            a0h[m][0] = Ah[t4 * AS2 + pl];           a0l[m][0] = Al[t4 * AS2 + pl];
            a0h[m][1] = Ah[t4 * AS2 + pl + 8];       a0l[m][1] = Al[t4 * AS2 + pl + 8];
            a0h[m][2] = Ah[(t4 + 4) * AS2 + pl];     a0l[m][2] = Al[(t4 + 4) * AS2 + pl];
            a0h[m][3] = Ah[(t4 + 4) * AS2 + pl + 8]; a0l[m][3] = Al[(t4 + 4) * AS2 + pl + 8];
        }

        // ---- issue cp.async gathers + carry blend coords for tile tn ----
        if (tn < ntw) {
            #pragma unroll
            for (int r = 0; r < 4; r++) {
                int idx = min(tn * 32 + r * 8 + pg, n - 1);
                float u = x[idx * 3 + 1], v = x[idx * 3 + 2];
                int pt = r * 8 + pg;
                CPA16(gbase + (pt * GQ + 0 + t4) * 16, tex_addr(emb0, 512, u, v, t4));
                CPA16(gbase + (pt * GQ + 4 + t4) * 16, tex_addr(emb1, 264, u, v, t4));
                CPA16(gbase + (pt * GQ + 8 + t4) * 16, tex_addr(emb2, 16,  u, v, t4));
            }
            #pragma unroll
            for (int r = 0; r < 2; r++) {
                int idx = min(tn * 32 + r * 16 + pb, n - 1);
                idb[r] = x[idx * 3 + 0]; ub[r] = x[idx * 3 + 1]; vb[r] = x[idx * 3 + 2];
            }
        }
        CPA_COMMIT();

        // ---- layer 1: 16 -> 64 (bias row folded), relu -> A1 frags ----
        uint32_t a1h[2][4][4], a1l[2][4][4];
        #pragma unroll
        for (int g = 0; g < 8; g++) {
            uint4 b = s.B1[g * 32 + lane];
            int kk = g >> 1, hf = g & 1;
            #pragma unroll
            for (int m = 0; m < 2; m++) {
                float c[4] = {0.0f, 0.0f, 0.0f, 0.0f};
                mma16816(c, a0h[m], b.x, b.y);
                mma16816(c, a0h[m], b.z, b.w);
                mma16816(c, a0l[m], b.x, b.y);
                splitpack(fmaxf(c[0], 0.0f), fmaxf(c[1], 0.0f),
                          a1h[m][kk][2 * hf + 0], a1l[m][kk][2 * hf + 0]);
                splitpack(fmaxf(c[2], 0.0f), fmaxf(c[3], 0.0f),
                          a1h[m][kk][2 * hf + 1], a1l[m][kk][2 * hf + 1]);
            }
        }

        // ---- layers 2+3 fused: a2 frags consumed immediately by layer 3 ----
        float c3[2][4];
        {
            float2 bb3 = *(const float2*)&s.b3s[2 * t4];
            #pragma unroll
            for (int m = 0; m < 2; m++) {
                c3[m][0] = bb3.x; c3[m][1] = bb3.y;
                c3[m][2] = bb3.x; c3[m][3] = bb3.y;
            }
        }
        uint32_t p2h[2][2], p2l[2][2];   // pending half-fragments (hf=0 words)
        #pragma unroll
        for (int g = 0; g < 8; g++) {
            uint4 bq0 = s.B2[(g * 4 + 0) * 32 + lane];
            uint4 bq1 = s.B2[(g * 4 + 1) * 32 + lane];
            uint4 bq2 = s.B2[(g * 4 + 2) * 32 + lane];
            uint4 bq3 = s.B2[(g * 4 + 3) * 32 + lane];
            float2 bb = *(const float2*)&s.b2s[8 * g + 2 * t4];
            int hf = g & 1;
            #pragma unroll
            for (int m = 0; m < 2; m++) {
                float c[4];
                c[0] = bb.x; c[1] = bb.y; c[2] = bb.x; c[3] = bb.y;
                mma16816(c, a1h[m][0], bq0.x, bq0.y);
                mma16816(c, a1h[m][0], bq0.z, bq0.w);
                mma16816(c, a1l[m][0], bq0.x, bq0.y);
                mma16816(c, a1h[m][1], bq1.x, bq1.y);
                mma16816(c, a1h[m][1], bq1.z, bq1.w);
                mma16816(c, a1l[m][1], bq1.x, bq1.y);
                mma16816(c, a1h[m][2], bq2.x, bq2.y);
                mma16816(c, a1h[m][2], bq2.z, bq2.w);
                mma16816(c, a1l[m][2], bq2.x, bq2.y);
                mma16816(c, a1h[m][3], bq3.x, bq3.y);
                mma16816(c, a1h[m][3], bq3.z, bq3.w);
                mma16816(c, a1l[m][3], bq3.x, bq3.y);
                uint32_t h01, l01, h23, l23;
                splitpack(fmaxf(c[0], 0.0f), fmaxf(c[1], 0.0f), h01, l01);
                splitpack(fmaxf(c[2], 0.0f), fmaxf(c[3], 0.0f), h23, l23);
                if (hf == 0) {
                    p2h[m][0] = h01; p2h[m][1] = h23;
                    p2l[m][0] = l01; p2l[m][1] = l23;
                } else {
                    // fragment for kk2 = g>>1 complete: layer-3 MMAs now
                    uint32_t a2hf[4] = {p2h[m][0], p2h[m][1], h01, h23};
                    uint32_t a2lf[4] = {p2l[m][0], p2l[m][1], l01, l23};
                    uint4 b3q = s.B3[(g >> 1) * 32 + lane];
                    mma16816(c3[m], a2hf, b3q.x, b3q.y);
                    mma16816(c3[m], a2hf, b3q.z, b3q.w);
                    mma16816(c3[m], a2lf, b3q.x, b3q.y);
                }
            }
        }

        // ---- write output ----
        #pragma unroll
        for (int m = 0; m < 2; m++) {
            int p0 = t * 32 + m * 16 + grp;
            int col = 2 * t4;
            if (col < 3) {
                if (p0 < n)     out[p0 * 3 + col]       = c3[m][0];
                if (p0 + 8 < n) out[(p0 + 8) * 3 + col] = c3[m][2];
            }
            if (col + 1 < 3) {
                if (p0 < n)     out[p0 * 3 + col + 1]       = c3[m][1];
                if (p0 + 8 < n) out[(p0 + 8) * 3 + col + 1] = c3[m][3];
            }
        }
    }
}

extern "C" void kernel_launch(void* const* d_in, const int* in_sizes, int n_in,
                              void* d_out, int out_size) {
    const float* x    = (const float*)d_in[0];
    const float4* e0  = (const float4*)d_in[1];
    const float4* e1  = (const float4*)d_in[2];
    const float4* e2  = (const float4*)d_in[3];
    const float* w1   = (const float*)d_in[4];
    const float* b1   = (const float*)d_in[5];
    const float* w2   = (const float*)d_in[6];
    const float* b2   = (const float*)d_in[7];
    const float* w3   = (const float*)d_in[8];
    const float* b3   = (const float*)d_in[9];
    float* out        = (float*)d_out;
    int n = in_sizes[0] / 3;
    (void)n_in; (void)out_size;
    cudaFuncSetAttribute(densegrid_kernel,
                         cudaFuncAttributeMaxDynamicSharedMemorySize, SMEM_BYTES);
    densegrid_kernel<<<NCTA, THREADS, SMEM_BYTES>>>(
        x, e0, e1, e2, w1, b1, w2, b2, w3, b3, out, n);
}